// round 11
// baseline (speedup 1.0000x reference)
#include <cuda_runtime.h>
#include <cuda_bf16.h>
#include <cstdint>

#define HEADS 8
#define DH    64
#define NPIX  1024
#define CC    512
#define NB    8
#define NBH   64
#define XSZ   (NB * CC * NPIX)   // 4194304
#define WSZ   (CC * CC)          // 262144

typedef unsigned long long u64;

// ---- scratch: bf16 hi/lo split operands (allocation-guard-safe globals) ----
__device__ __align__(16) __nv_bfloat16 g_qh[NBH * NPIX * DH];  // [bh][n][d]
__device__ __align__(16) __nv_bfloat16 g_ql[NBH * NPIX * DH];
__device__ __align__(16) __nv_bfloat16 g_kh[NBH * NPIX * DH];
__device__ __align__(16) __nv_bfloat16 g_kl[NBH * NPIX * DH];
__device__ __align__(16) __nv_bfloat16 g_vh[NBH * NPIX * DH];  // [bh][n][d]
__device__ __align__(16) __nv_bfloat16 g_vl[NBH * NPIX * DH];
__device__ __align__(16) __nv_bfloat16 g_ph[HEADS * NPIX * DH]; // [h][n][d]
__device__ __align__(16) __nv_bfloat16 g_pl[HEADS * NPIX * DH];
__device__ __align__(16) __nv_bfloat16 g_xh[XSZ];   // x  [b][c][n]
__device__ __align__(16) __nv_bfloat16 g_xl[XSZ];
__device__ __align__(16) __nv_bfloat16 g_eh[XSZ];   // d  [b][c][n]
__device__ __align__(16) __nv_bfloat16 g_el[XSZ];
__device__ __align__(16) __nv_bfloat16 g_wh[3 * WSZ]; // Wq|Wk|Wv [o][c]
__device__ __align__(16) __nv_bfloat16 g_wl[3 * WSZ];

__device__ __forceinline__ void bsplit(float y, __nv_bfloat16 &hi, __nv_bfloat16 &lo) {
    hi = __float2bfloat16(y);
    lo = __float2bfloat16(y - __bfloat162float(hi));
}

// ---- mma.sync / ldmatrix / cp.async primitives (baseline PTX, sm_80+) ----
__device__ __forceinline__ uint32_t smem_to_u32(const void *p) {
    uint32_t a;
    asm("{ .reg .u64 t; cvta.to.shared.u64 t, %1; cvt.u32.u64 %0, t; }"
        : "=r"(a) : "l"(p));
    return a;
}
__device__ __forceinline__ void ldsm4(uint32_t *r, uint32_t addr) {
    asm volatile("ldmatrix.sync.aligned.m8n8.x4.shared.b16 {%0,%1,%2,%3}, [%4];"
                 : "=r"(r[0]), "=r"(r[1]), "=r"(r[2]), "=r"(r[3]) : "r"(addr));
}
__device__ __forceinline__ void ldsm4t(uint32_t *r, uint32_t addr) {
    asm volatile("ldmatrix.sync.aligned.m8n8.x4.trans.shared.b16 {%0,%1,%2,%3}, [%4];"
                 : "=r"(r[0]), "=r"(r[1]), "=r"(r[2]), "=r"(r[3]) : "r"(addr));
}
__device__ __forceinline__ void hmma(float *c, const uint32_t *a, uint32_t b0, uint32_t b1) {
    asm volatile(
        "mma.sync.aligned.m16n8k16.row.col.f32.bf16.bf16.f32 "
        "{%0,%1,%2,%3}, {%4,%5,%6,%7}, {%8,%9}, {%0,%1,%2,%3};"
        : "+f"(c[0]), "+f"(c[1]), "+f"(c[2]), "+f"(c[3])
        : "r"(a[0]), "r"(a[1]), "r"(a[2]), "r"(a[3]), "r"(b0), "r"(b1));
}
__device__ __forceinline__ void cp16(uint32_t s, const void *g) {
    asm volatile("cp.async.cg.shared.global [%0], [%1], 16;" :: "r"(s), "l"(g));
}
#define CP_COMMIT() asm volatile("cp.async.commit_group;" ::: "memory")
#define CP_WAIT0()  asm volatile("cp.async.wait_group 0;" ::: "memory")
#define CP_WAIT1()  asm volatile("cp.async.wait_group 1;" ::: "memory")

__device__ __forceinline__ uint32_t packbf(float e, float o) {
    uint32_t r;
    asm("cvt.rn.bf16x2.f32 %0, %1, %2;" : "=r"(r) : "f"(o), "f"(e));
    return r;
}
__device__ __forceinline__ float lo_of(uint32_t r) { return __uint_as_float(r << 16); }
__device__ __forceinline__ float hi_of(uint32_t r) { return __uint_as_float(r & 0xFFFF0000u); }

// ================= split inputs/weights to bf16 hi/lo =================
__global__ void split_kernel(const float *__restrict__ x, const float *__restrict__ dsrc,
                             const float *__restrict__ Wq, const float *__restrict__ Wk,
                             const float *__restrict__ Wv) {
    size_t i4 = ((size_t)blockIdx.x * 256 + threadIdx.x) * 4;
    const float *s;
    __nv_bfloat16 *oh, *ol;
    size_t off;
    if (i4 < (size_t)XSZ) {
        s = x; oh = g_xh; ol = g_xl; off = i4;
    } else if (i4 < 2 * (size_t)XSZ) {
        s = dsrc; oh = g_eh; ol = g_el; off = i4 - XSZ;
    } else {
        size_t wi = i4 - 2 * (size_t)XSZ;
        int p = (int)(wi / WSZ);
        off = wi - (size_t)p * WSZ;
        s = (p == 0) ? Wq : (p == 1 ? Wk : Wv);
        oh = g_wh + (size_t)p * WSZ;
        ol = g_wl + (size_t)p * WSZ;
    }
    float4 v = *(const float4 *)&s[off];
    __align__(8) __nv_bfloat16 h[4], l[4];
    bsplit(v.x, h[0], l[0]); bsplit(v.y, h[1], l[1]);
    bsplit(v.z, h[2], l[2]); bsplit(v.w, h[3], l[3]);
    *(u64 *)&oh[off] = *(const u64 *)h;
    *(u64 *)&ol[off] = *(const u64 *)l;
}

// ================= pos = rel_h + rel_w (split) =================
__global__ void pos_kernel(const float *__restrict__ rel_h,
                           const float *__restrict__ rel_w) {
    int idx = blockIdx.x * 256 + threadIdx.x;   // (h*1024+n)*64+d
    int d  = idx & 63;
    int n  = (idx >> 6) & 1023;
    int hh = idx >> 16;
    int w  = n >> 5;
    int hw = n & 31;
    float v = rel_h[(hh * DH + d) * 32 + hw] + rel_w[(hh * DH + d) * 32 + w];
    __nv_bfloat16 bh_, bl_;
    bsplit(v, bh_, bl_);
    g_ph[idx] = bh_;
    g_pl[idx] = bl_;
}

// ================= HMMA projection GEMMs (unchanged from passing R8) ========
#define PB_AH 0
#define PB_AL 8704
#define PB_WH 17408
#define PB_WL 27648
#define PB_SZ 37888
#define PROJ_SMEM (2 * PB_SZ)

__device__ __forceinline__ void stage_proj(uint32_t bufsb,
                                           const __nv_bfloat16 *ah, const __nv_bfloat16 *al,
                                           const __nv_bfloat16 *wh, const __nv_bfloat16 *wl,
                                           int m0, int o0, int k0, int tid) {
    #pragma unroll
    for (int l = 0; l < 2; l++) {
        int c = tid + l * 256;
        int k = c >> 4;
        cp16(bufsb + PB_AH + k * 272 + (c & 15) * 16,
             ah + (size_t)(k0 + k) * NPIX + m0 + (c & 15) * 8);
    }
    #pragma unroll
    for (int l = 0; l < 2; l++) {
        int c = tid + l * 256;
        int k = c >> 4;
        cp16(bufsb + PB_AL + k * 272 + (c & 15) * 16,
             al + (size_t)(k0 + k) * NPIX + m0 + (c & 15) * 8);
    }
    #pragma unroll
    for (int l = 0; l < 2; l++) {
        int c = tid + l * 256;
        int o = c >> 2;
        cp16(bufsb + PB_WH + o * 80 + (c & 3) * 16,
             wh + (size_t)(o0 + o) * CC + k0 + (c & 3) * 8);
    }
    #pragma unroll
    for (int l = 0; l < 2; l++) {
        int c = tid + l * 256;
        int o = c >> 2;
        cp16(bufsb + PB_WL + o * 80 + (c & 3) * 16,
             wl + (size_t)(o0 + o) * CC + k0 + (c & 3) * 8);
    }
}

__global__ __launch_bounds__(256, 2) void proj_kernel(
    const float *__restrict__ bq, const float *__restrict__ bk,
    const float *__restrict__ bv) {
    extern __shared__ __align__(16) char psmem[];
    const uint32_t sb = smem_to_u32(psmem);

    const int p  = blockIdx.z;
    const int b  = blockIdx.y;
    const int m0 = (blockIdx.x >> 2) * 128;
    const int o0 = (blockIdx.x & 3) * 128;

    const int tid  = threadIdx.x;
    const int w    = tid >> 5;
    const int lane = tid & 31;
    const int wm   = w & 3;
    const int wn   = w >> 2;

    const __nv_bfloat16 *ah = ((p == 0) ? g_xh : g_eh) + (size_t)b * CC * NPIX;
    const __nv_bfloat16 *al = ((p == 0) ? g_xl : g_el) + (size_t)b * CC * NPIX;
    const __nv_bfloat16 *wh = g_wh + (size_t)p * WSZ;
    const __nv_bfloat16 *wl = g_wl + (size_t)p * WSZ;
    const float *bias = (p == 0) ? bq : (p == 1 ? bk : bv);

    const uint32_t at_base = (((lane >> 4) * 8) + (lane & 7)) * 272 +
                             wm * 64 + ((lane >> 3) & 1) * 16;
    const uint32_t wb_base = (((lane >> 4) * 8) + (lane & 7)) * 80 +
                             ((lane >> 3) & 1) * 16;

    float s[2][8][4];
    #pragma unroll
    for (int mt = 0; mt < 2; mt++)
        #pragma unroll
        for (int j = 0; j < 8; j++)
            #pragma unroll
            for (int e = 0; e < 4; e++) s[mt][j][e] = 0.f;

    stage_proj(sb, ah, al, wh, wl, m0, o0, 0, tid);
    CP_COMMIT();

    for (int kc = 0; kc < 16; kc++) {
        const uint32_t buf = sb + (kc & 1) * PB_SZ;
        CP_WAIT0();
        __syncthreads();
        if (kc < 15) {
            stage_proj(sb + ((kc + 1) & 1) * PB_SZ, ah, al, wh, wl,
                       m0, o0, (kc + 1) * 32, tid);
            CP_COMMIT();
        }
        #pragma unroll
        for (int ks = 0; ks < 2; ks++) {
            uint32_t aH[2][4], aL[2][4];
            #pragma unroll
            for (int mt = 0; mt < 2; mt++) {
                ldsm4t(aH[mt], buf + PB_AH + ks * 4352 + at_base + mt * 32);
                ldsm4t(aL[mt], buf + PB_AL + ks * 4352 + at_base + mt * 32);
            }
            #pragma unroll
            for (int ng = 0; ng < 4; ng++) {
                uint32_t bH[4], bL[4];
                uint32_t wrow = (wn * 64 + ng * 16) * 80;
                ldsm4(bH, buf + PB_WH + wrow + wb_base + ks * 32);
                ldsm4(bL, buf + PB_WL + wrow + wb_base + ks * 32);
                #pragma unroll
                for (int mt = 0; mt < 2; mt++) {
                    hmma(s[mt][2 * ng],     aH[mt], bH[0], bH[1]);
                    hmma(s[mt][2 * ng + 1], aH[mt], bH[2], bH[3]);
                    hmma(s[mt][2 * ng],     aH[mt], bL[0], bL[1]);
                    hmma(s[mt][2 * ng + 1], aH[mt], bL[2], bL[3]);
                    hmma(s[mt][2 * ng],     aL[mt], bH[0], bH[1]);
                    hmma(s[mt][2 * ng + 1], aL[mt], bH[2], bH[3]);
                }
            }
        }
    }

    const int o_base = o0 + wn * 64;
    const int head = o_base >> 6;
    const int bhx  = b * 8 + head;
    __nv_bfloat16 *dh = (p == 0) ? g_qh : (p == 1 ? g_kh : g_vh);
    __nv_bfloat16 *dl = (p == 0) ? g_ql : (p == 1 ? g_kl : g_vl);

    float2 bb[8];
    #pragma unroll
    for (int j = 0; j < 8; j++)
        bb[j] = *(const float2 *)&bias[o_base + j * 8 + 2 * (lane & 3)];

    #pragma unroll
    for (int mt = 0; mt < 2; mt++) {
        int r = wm * 32 + mt * 16 + (lane >> 2);
        size_t rowA = ((size_t)bhx * NPIX + m0 + r) * DH;
        size_t rowB = ((size_t)bhx * NPIX + m0 + r + 8) * DH;
        #pragma unroll
        for (int j = 0; j < 8; j++) {
            int d0 = j * 8 + 2 * (lane & 3);
            float y0 = s[mt][j][0] + bb[j].x;
            float y1 = s[mt][j][1] + bb[j].y;
            float y2 = s[mt][j][2] + bb[j].x;
            float y3 = s[mt][j][3] + bb[j].y;
            uint32_t h01 = packbf(y0, y1);
            uint32_t h23 = packbf(y2, y3);
            uint32_t l01 = packbf(y0 - lo_of(h01), y1 - hi_of(h01));
            uint32_t l23 = packbf(y2 - lo_of(h23), y3 - hi_of(h23));
            *(uint32_t *)&dh[rowA + d0] = h01;
            *(uint32_t *)&dl[rowA + d0] = l01;
            *(uint32_t *)&dh[rowB + d0] = h23;
            *(uint32_t *)&dl[rowB + d0] = l23;
        }
    }
}

// ================= HMMA flash attention v4: software-pipelined =============
// R8 geometry (512 thr, warp 16 rows x 32 cols) + S(n+1)/PV(n) overlap:
// softmax(n) -> [S(n+1) || PV(n)] with phase-shifted B/V cp.async rings.
#define SM_AH   0
#define SM_AL   34816
#define BUF0    69632
#define BUF1    122880
#define OB_BH   0
#define OB_BL   17408
#define OB_VH   34816
#define OB_VL   44032
#define SC_OACC 4096
#define SC_OT   40960
#define ATTN_SMEM 176128

__device__ __forceinline__ void stage_b(uint32_t bufsb, int bh, int j0, int tid) {
    #pragma unroll
    for (int l = 0; l < 4; l++) {
        int c = tid + l * 512;
        int mat = c >> 10, cc = c & 1023;
        int j = cc >> 4, k8 = (cc & 15) * 8;
        const __nv_bfloat16 *s = (k8 < 64)
            ? (mat ? g_kl : g_kh) + ((size_t)bh * NPIX + j0 + j) * DH + k8
            : (mat ? g_ql : g_qh) + ((size_t)bh * NPIX + j0 + j) * DH + (k8 - 64);
        cp16(bufsb + (mat ? OB_BL : OB_BH) + j * 272 + k8 * 2, s);
    }
}
__device__ __forceinline__ void stage_v(uint32_t bufsb, int bh, int j0, int tid) {
    #pragma unroll
    for (int l = 0; l < 2; l++) {
        int c = tid + l * 512;
        int mat = c >> 9, cc = c & 511;
        int j = cc >> 3, d8 = (cc & 7) * 8;
        const __nv_bfloat16 *s =
            (mat ? g_vl : g_vh) + ((size_t)bh * NPIX + j0 + j) * DH + d8;
        cp16(bufsb + (mat ? OB_VL : OB_VH) + j * 144 + d8 * 2, s);
    }
}

__global__ __launch_bounds__(512, 1) void attn_kernel(float *__restrict__ out) {
    extern __shared__ __align__(16) char smem[];
    const uint32_t sb = smem_to_u32(smem);

    const int tid  = threadIdx.x;
    const int w    = tid >> 5;
    const int lane = tid & 31;
    const int wm   = w & 7;
    const int wn   = w >> 3;
    const int i0   = blockIdx.x * 128;
    const int bh   = blockIdx.y;
    const int hd   = bh & 7;

    const uint32_t a_off = (lane & 15) * 272 + (lane >> 4) * 16;
    const uint32_t b_off = ((lane >> 4) * 8 + (lane & 7)) * 272 + ((lane >> 3) & 1) * 16;
    const uint32_t v_off = (((lane >> 3) & 1) * 8 + (lane & 7)) * 144 + (lane >> 4) * 16;

    // prologue: B(0),V(0) -> BUF0 (group 1); B(1) -> BUF1 (group 2)
    stage_b(sb + BUF0, bh, 0, tid);
    stage_v(sb + BUF0, bh, 0, tid);
    CP_COMMIT();
    stage_b(sb + BUF1, bh, 64, tid);
    CP_COMMIT();

    // stage A = [q_i | pos_i] hi/lo (plain loads, once)
    for (int c = tid; c < 4096; c += 512) {
        int mat = c >> 11, cc = c & 2047;
        int i = cc >> 4, k8 = (cc & 15) * 8;
        const __nv_bfloat16 *s = (k8 < 64)
            ? (mat ? g_ql : g_qh) + ((size_t)bh * NPIX + i0 + i) * DH + k8
            : (mat ? g_pl : g_ph) + ((size_t)hd * NPIX + i0 + i) * DH + (k8 - 64);
        *(uint4 *)(smem + (mat ? SM_AL : SM_AH) + i * 272 + k8 * 2) = *(const uint4 *)s;
    }

    float mv[2] = {-1e30f, -1e30f}, lv[2] = {0.f, 0.f};
    float O[8][4];
    #pragma unroll
    for (int c = 0; c < 8; c++)
        #pragma unroll
        for (int e = 0; e < 4; e++) O[c][e] = 0.f;
    float s[4][4];

    CP_WAIT1();          // B(0),V(0) landed
    __syncthreads();

    // ---- S(0) from BUF0 ----
    #pragma unroll
    for (int np = 0; np < 4; np++)
        #pragma unroll
        for (int e = 0; e < 4; e++) s[np][e] = 0.f;
    #pragma unroll
    for (int ks = 0; ks < 8; ks++) {
        uint32_t aH[4], aL[4];
        uint32_t abase = wm * 16 * 272 + ks * 32 + a_off;
        ldsm4(aH, sb + SM_AH + abase);
        ldsm4(aL, sb + SM_AL + abase);
        #pragma unroll
        for (int nt = 0; nt < 2; nt++) {
            uint32_t bH[4], bL[4];
            uint32_t bbase = (wn * 32 + nt * 16) * 272 + ks * 32 + b_off;
            ldsm4(bH, sb + BUF0 + OB_BH + bbase);
            ldsm4(bL, sb + BUF0 + OB_BL + bbase);
            hmma(s[2 * nt],     aH, bH[0], bH[1]);
            hmma(s[2 * nt + 1], aH, bH[2], bH[3]);
            hmma(s[2 * nt],     aH, bL[0], bL[1]);
            hmma(s[2 * nt + 1], aH, bL[2], bL[3]);
            hmma(s[2 * nt],     aL, bH[0], bH[1]);
            hmma(s[2 * nt + 1], aL, bH[2], bH[3]);
        }
    }

    for (int n = 0; n < 16; n++) {
        // ---- softmax(n) (warp-local over own 32 cols) ----
        float pm0 = s[0][0], pm1 = s[0][2];
        #pragma unroll
        for (int np = 0; np < 4; np++) {
            pm0 = fmaxf(pm0, fmaxf(s[np][0], s[np][1]));
            pm1 = fmaxf(pm1, fmaxf(s[np][2], s[np][3]));
        }
        pm0 = fmaxf(pm0, __shfl_xor_sync(0xffffffffu, pm0, 1));
        pm0 = fmaxf(pm0, __shfl_xor_sync(0xffffffffu, pm0, 2));
        pm1 = fmaxf(pm1, __shfl_xor_sync(0xffffffffu, pm1, 1));
        pm1 = fmaxf(pm1, __shfl_xor_sync(0xffffffffu, pm1, 2));
        float mn0 = fmaxf(mv[0], pm0), mn1 = fmaxf(mv[1], pm1);
        float sc0 = __expf(mv[0] - mn0), sc1 = __expf(mv[1] - mn1);
        mv[0] = mn0; mv[1] = mn1;
        float sum0 = 0.f, sum1 = 0.f;
        #pragma unroll
        for (int np = 0; np < 4; np++) {
            s[np][0] = __expf(s[np][0] - mn0);
            s[np][1] = __expf(s[np][1] - mn0);
            s[np][2] = __expf(s[np][2] - mn1);
            s[np][3] = __expf(s[np][3] - mn1);
            sum0 += s[np][0] + s[np][1];
            sum1 += s[np][2] + s[np][3];
        }
        sum0 += __shfl_xor_sync(0xffffffffu, sum0, 1);
        sum0 += __shfl_xor_sync(0xffffffffu, sum0, 2);
        sum1 += __shfl_xor_sync(0xffffffffu, sum1, 1);
        sum1 += __shfl_xor_sync(0xffffffffu, sum1, 2);
        lv[0] = lv[0] * sc0 + sum0;
        lv[1] = lv[1] * sc1 + sum1;
        #pragma unroll
        for (int c = 0; c < 8; c++) {
            O[c][0] *= sc0; O[c][1] *= sc0;
            O[c][2] *= sc1; O[c][3] *= sc1;
        }
        // P fragments from acc regs (hi/lo split)
        uint32_t pH[2][4], pL[2][4];
        #pragma unroll
        for (int kk = 0; kk < 2; kk++) {
            #pragma unroll
            for (int hh = 0; hh < 2; hh++) {
                float e0 = s[2 * kk + hh][0], o0 = s[2 * kk + hh][1];
                float e1 = s[2 * kk + hh][2], o1 = s[2 * kk + hh][3];
                uint32_t h0 = packbf(e0, o0);
                uint32_t h1 = packbf(e1, o1);
                pH[kk][2 * hh]     = h0;
                pH[kk][2 * hh + 1] = h1;
                pL[kk][2 * hh]     = packbf(e0 - lo_of(h0), o0 - hi_of(h0));
                pL[kk][2 * hh + 1] = packbf(e1 - lo_of(h1), o1 - hi_of(h1));
            }
        }

        // ---- stage B(n+2), V(n+1); one group per iteration ----
        __syncthreads();   // all warps done reading B(n) slot / V(n-1) slot
        if (n < 14) stage_b(sb + ((n & 1) ? BUF1 : BUF0), bh, (n + 2) * 64, tid);
        if (n < 15) stage_v(sb + (((n + 1) & 1) ? BUF1 : BUF0), bh, (n + 1) * 64, tid);
        CP_COMMIT();
        CP_WAIT1();        // B(n+1), V(n) landed
        __syncthreads();

        const uint32_t bufS = sb + (((n + 1) & 1) ? BUF1 : BUF0);
        const uint32_t bufV = sb + ((n & 1) ? BUF1 : BUF0);

        // ---- S(n+1) (independent of softmax(n)) ----
        if (n < 15) {
            #pragma unroll
            for (int np = 0; np < 4; np++)
                #pragma unroll
                for (int e = 0; e < 4; e++) s[np][e] = 0.f;
            #pragma unroll
            for (int ks = 0; ks < 8; ks++) {
                uint32_t aH[4], aL[4];
                uint32_t abase = wm * 16 * 272 + ks * 32 + a_off;
                ldsm4(aH, sb + SM_AH + abase);
                ldsm4(aL, sb + SM_AL + abase);
                #pragma unroll
                for (int nt = 0; nt < 2; nt++) {
                    uint32_t bH[4], bL[4];
                    uint32_t bbase = (wn * 32 + nt * 16) * 272 + ks * 32 + b_off;
                    ldsm4(bH, bufS + OB_BH + bbase);
                    ldsm4(bL, bufS + OB_BL + bbase);
                    hmma(s[2 * nt],     aH, bH[0], bH[1]);
                    hmma(s[2 * nt + 1], aH, bH[2], bH[3]);
                    hmma(s[2 * nt],     aH, bL[0], bL[1]);
                    hmma(s[2 * nt + 1], aH, bL[2], bL[3]);
                    hmma(s[2 * nt],     aL, bH[0], bH[1]);
                    hmma(s[2 * nt + 1], aL, bH[2], bH[3]);
                }
            }
        }

        // ---- PV(n) (interleaves with S(n+1): independent chains) ----
        #pragma unroll
        for (int kk = 0; kk < 2; kk++) {
            uint32_t vrow = (wn * 32 + kk * 16) * 144;
            #pragma unroll
            for (int dp = 0; dp < 4; dp++) {
                uint32_t vH[4], vL[4];
                uint32_t vbase = vrow + dp * 32 + v_off;
                ldsm4t(vH, bufV + OB_VH + vbase);
                ldsm4t(vL, bufV + OB_VL + vbase);
                hmma(O[2 * dp],     pH[kk], vH[0], vH[1]);
                hmma(O[2 * dp + 1], pH[kk], vH[2], vH[3]);
                hmma(O[2 * dp],     pH[kk], vL[0], vL[1]);
                hmma(O[2 * dp + 1], pH[kk], vL[2], vL[3]);
                hmma(O[2 * dp],     pL[kk], vH[0], vH[1]);
                hmma(O[2 * dp + 1], pL[kk], vH[2], vH[3]);
            }
        }
    }

    // ---- epilogue: merge the two column-halves, normalize, store ----
    __syncthreads();
    float *sm_m = (float *)smem;
    float *sm_l = (float *)(smem + 1024);
    const int r0 = wm * 16 + (lane >> 2);
    sm_m[wn * 128 + r0]     = mv[0];
    sm_m[wn * 128 + r0 + 8] = mv[1];
    sm_l[wn * 128 + r0]     = lv[0];
    sm_l[wn * 128 + r0 + 8] = lv[1];
    __syncthreads();
    float fs[2], lt[2];
    #pragma unroll
    for (int hh = 0; hh < 2; hh++) {
        int rr = r0 + 8 * hh;
        float mo = sm_m[(1 ^ wn) * 128 + rr];
        float lo2 = sm_l[(1 ^ wn) * 128 + rr];
        float mt = fmaxf(mv[hh], mo);
        fs[hh] = __expf(mv[hh] - mt);
        float fo = __expf(mo - mt);
        lt[hh] = lv[hh] * fs[hh] + lo2 * fo;
    }
    float *oacc = (float *)(smem + SC_OACC);
    const int cq = 2 * (lane & 3);
    __syncthreads();
    if (wn == 1) {
        #pragma unroll
        for (int c = 0; c < 8; c++)
            #pragma unroll
            for (int hh = 0; hh < 2; hh++) {
                int rr = r0 + 8 * hh;
                oacc[rr * 68 + 8 * c + cq]     = O[c][2 * hh]     * fs[hh];
                oacc[rr * 68 + 8 * c + cq + 1] = O[c][2 * hh + 1] * fs[hh];
            }
    }
    __syncthreads();
    float *ot = (float *)(smem + SC_OT);
    if (wn == 0) {
        #pragma unroll
        for (int c = 0; c < 8; c++)
            #pragma unroll
            for (int hh = 0; hh < 2; hh++) {
                int rr = r0 + 8 * hh;
                float rlt = 1.0f / lt[hh];
                int d0 = 8 * c + cq;
                ot[d0 * 136 + rr] =
                    (O[c][2 * hh] * fs[hh] + oacc[rr * 68 + d0]) * rlt;
                ot[(d0 + 1) * 136 + rr] =
                    (O[c][2 * hh + 1] * fs[hh] + oacc[rr * 68 + d0 + 1]) * rlt;
            }
    }
    __syncthreads();
    {
        int dr = tid >> 3, ch = (tid & 7) * 16;
        const float *src = ot + dr * 136 + ch;
        float *ob = out + (((size_t)(bh >> 3) * 512) + hd * 64 + dr) * NPIX + i0 + ch;
        #pragma unroll
        for (int e = 0; e < 4; e++)
            *(float4 *)(ob + 4 * e) = *(const float4 *)(src + 4 * e);
    }
}

// ================= launch =================
extern "C" void kernel_launch(void *const *d_in, const int *in_sizes, int n_in,
                              void *d_out, int out_size) {
    const float *x     = (const float *)d_in[0];
    const float *d     = (const float *)d_in[1];
    const float *Wq    = (const float *)d_in[2];
    const float *bq    = (const float *)d_in[3];
    const float *Wk    = (const float *)d_in[4];
    const float *bk    = (const float *)d_in[5];
    const float *Wv    = (const float *)d_in[6];
    const float *bv    = (const float *)d_in[7];
    const float *rel_h = (const float *)d_in[8];
    const float *rel_w = (const float *)d_in[9];
    float *out = (float *)d_out;

    cudaFuncSetAttribute(proj_kernel,
                         cudaFuncAttributeMaxDynamicSharedMemorySize, PROJ_SMEM);
    cudaFuncSetAttribute(attn_kernel,
                         cudaFuncAttributeMaxDynamicSharedMemorySize, ATTN_SMEM);

    split_kernel<<<8960, 256>>>(x, d, Wq, Wk, Wv);
    proj_kernel<<<dim3(32, NB, 3), 256, PROJ_SMEM>>>(bq, bk, bv);
    pos_kernel<<<HEADS * NPIX * DH / 256, 256>>>(rel_h, rel_w);
    attn_kernel<<<dim3(8, NBH), 512, ATTN_SMEM>>>(out);
}